// round 9
// baseline (speedup 1.0000x reference)
#include <cuda_runtime.h>
#include <cstdint>

// z = sum_{p,q,r} C[p*9+q*3+r] * u0_p * u1_q * u2_r,  u_i = (1, cos x_i, sin x_i)
__device__ float d_C[27];

// ---------------------------------------------------------------------------
// Kernel 1: build the 27 trilinear coefficients from q_weights (18 floats).
// Single warp, no block barriers. All 18 sincos computed in parallel up
// front (one per lane) and broadcast via shfl; gate chain fully unrolled.
// ---------------------------------------------------------------------------
__global__ void build_coeffs(const float* __restrict__ qw) {
    __shared__ float Ure[8][8];   // [m][j]
    __shared__ float Uim[8][8];
    __shared__ float Aj[8][8];    // A[j][k]

    const unsigned FULL = 0xFFFFFFFFu;
    const int lane = threadIdx.x;

    // Parallel sincos of all 18 half-angles (lanes 0..17).
    float ang = (lane < 18) ? 0.5f * qw[lane] : 0.f;
    float sh, ch;
    __sincosf(ang, &sh, &ch);

    // Lanes 0..7 simulate basis column j = lane.
    const int j = lane & 7;
    float sr[8], si[8];
    #pragma unroll
    for (int m = 0; m < 8; m++) { sr[m] = 0.f; si[m] = 0.f; }
    sr[j] = 1.0f;

    #pragma unroll
    for (int g = 0; g < 9; g++) {          // gate index: layer = g/3, qubit = g%3
        const int bit = 4 >> (g % 3);
        float cy = __shfl_sync(FULL, ch, 2 * g);
        float sy = __shfl_sync(FULL, sh, 2 * g);
        float cz = __shfl_sync(FULL, ch, 2 * g + 1);
        float sz = __shfl_sync(FULL, sh, 2 * g + 1);

        // RY
        #pragma unroll
        for (int m = 0; m < 8; m++) {
            if (m & bit) continue;
            int m1 = m | bit;
            float ar = sr[m],  ai = si[m];
            float br = sr[m1], bi = si[m1];
            sr[m]  = cy * ar - sy * br;  si[m]  = cy * ai - sy * bi;
            sr[m1] = sy * ar + cy * br;  si[m1] = sy * ai + cy * bi;
        }
        // RZ
        #pragma unroll
        for (int m = 0; m < 8; m++) {
            float ar = sr[m], ai = si[m];
            if (m & bit) { sr[m] = cz * ar - sz * ai; si[m] = cz * ai + sz * ar; }
            else         { sr[m] = cz * ar + sz * ai; si[m] = cz * ai - sz * ar; }
        }
        // End of layer: CNOT01 then CNOT12
        if (g % 3 == 2) {
            #pragma unroll
            for (int m = 4; m < 6; m++) {   // CNOT01: swap (4,6),(5,7)
                int m1 = m | 2; float tmp;
                tmp = sr[m]; sr[m] = sr[m1]; sr[m1] = tmp;
                tmp = si[m]; si[m] = si[m1]; si[m1] = tmp;
            }
            #pragma unroll
            for (int m = 2; m < 8; m += 4) { // CNOT12: swap (2,3),(6,7)
                int m1 = m | 1; float tmp;
                tmp = sr[m]; sr[m] = sr[m1]; sr[m1] = tmp;
                tmp = si[m]; si[m] = si[m1]; si[m1] = tmp;
            }
        }
    }

    if (lane < 8) {
        #pragma unroll
        for (int m = 0; m < 8; m++) { Ure[m][j] = sr[m]; Uim[m][j] = si[m]; }
    }
    __syncwarp();

    // A[j][k] = sum_m sign(m) (Ure[m][j]Ure[m][k] + Uim[m][j]Uim[m][k]);
    // 64 entries, 2 per lane.
    #pragma unroll
    for (int h = 0; h < 2; h++) {
        int e = lane + h * 32;
        int jj = e >> 3, kk = e & 7;
        float a = 0.f;
        #pragma unroll
        for (int m = 0; m < 8; m++) {
            float sgn = (m & 4) ? -1.f : 1.f;
            a += sgn * (Ure[m][jj] * Ure[m][kk] + Uim[m][jj] * Uim[m][kk]);
        }
        Aj[jj][kk] = a;
    }
    __syncwarp();

    // Contraction: each lane accumulates its 2 (j,k) rank-1 contributions
    // into a private 27-vector, then warp tree-reduce.
    float cpart[27];
    #pragma unroll
    for (int i = 0; i < 27; i++) cpart[i] = 0.f;

    #pragma unroll
    for (int h = 0; h < 2; h++) {
        int e = lane + h * 32;
        int jj = e >> 3, kk = e & 7;
        float a = Aj[jj][kk];

        // g-vector per qubit: a==b -> (0.5, a?-0.5:0.5, 0); a!=b -> (0,0,0.5)
        float g0[3], g1[3], g2[3];
        {
            int aa = (jj >> 2) & 1, bb = (kk >> 2) & 1;
            g0[0] = (aa == bb) ? 0.5f : 0.f;
            g0[1] = (aa == bb) ? (aa ? -0.5f : 0.5f) : 0.f;
            g0[2] = (aa != bb) ? 0.5f : 0.f;
        }
        {
            int aa = (jj >> 1) & 1, bb = (kk >> 1) & 1;
            g1[0] = (aa == bb) ? 0.5f : 0.f;
            g1[1] = (aa == bb) ? (aa ? -0.5f : 0.5f) : 0.f;
            g1[2] = (aa != bb) ? 0.5f : 0.f;
        }
        {
            int aa = jj & 1, bb = kk & 1;
            g2[0] = (aa == bb) ? 0.5f : 0.f;
            g2[1] = (aa == bb) ? (aa ? -0.5f : 0.5f) : 0.f;
            g2[2] = (aa != bb) ? 0.5f : 0.f;
        }

        #pragma unroll
        for (int p = 0; p < 3; p++) {
            float ag0 = a * g0[p];
            #pragma unroll
            for (int q = 0; q < 3; q++) {
                float ag01 = ag0 * g1[q];
                #pragma unroll
                for (int r = 0; r < 3; r++)
                    cpart[p * 9 + q * 3 + r] = fmaf(ag01, g2[r], cpart[p * 9 + q * 3 + r]);
            }
        }
    }

    // Warp reduction (5 levels) of each of the 27 sums.
    #pragma unroll
    for (int off = 16; off > 0; off >>= 1) {
        #pragma unroll
        for (int i = 0; i < 27; i++)
            cpart[i] += __shfl_xor_sync(FULL, cpart[i], off);
    }
    if (lane < 27) d_C[lane] = cpart[lane];
}

// ---------------------------------------------------------------------------
// Kernel 2: evaluate, launched with Programmatic Stream Serialization.
// All 8 input loads issued BEFORE cudaGridDependencySynchronize(); d_C read
// only after the dependency sync. Eval is at the measured streaming floor
// (~3.3 TB/s for this access shape on this platform).
// ---------------------------------------------------------------------------
static constexpr int SPT = 8;
static constexpr int BLOCK = 256;

__global__ void __launch_bounds__(BLOCK) vqc_eval(const float4* __restrict__ in,
                                                  float* __restrict__ out, int B) {
    const int T = gridDim.x * BLOCK;
    const int t = blockIdx.x * BLOCK + threadIdx.x;

    // Front-batch ALL loads — independent of build_coeffs' output.
    float4 x[SPT];
    #pragma unroll
    for (int k = 0; k < SPT; k++) {
        int i = t + k * T;
        i = (i < B) ? i : (B - 1);
        x[k] = in[(size_t)i * 2];     // first 16B of the 32B row
    }

    cudaGridDependencySynchronize();

    __shared__ float cs[27];
    if (threadIdx.x < 27) cs[threadIdx.x] = d_C[threadIdx.x];
    __syncthreads();

    #pragma unroll
    for (int k = 0; k < SPT; k++) {
        float C0, S0, C1, S1, C2, S2;
        __sincosf(x[k].x, &S0, &C0);
        __sincosf(x[k].y, &S1, &C1);
        __sincosf(x[k].z, &S2, &C2);

        float u0[3] = {1.f, C0, S0};
        float u1[3] = {1.f, C1, S1};
        float z = 0.f;
        #pragma unroll
        for (int p = 0; p < 3; p++) {
            #pragma unroll
            for (int q = 0; q < 3; q++) {
                const float* c3 = &cs[p * 9 + q * 3];
                float w = c3[0];
                w = fmaf(c3[1], C2, w);
                w = fmaf(c3[2], S2, w);
                z = fmaf(u0[p] * u1[q], w, z);
            }
        }
        int i = t + k * T;
        if (i < B) out[i] = z;
    }
}

extern "C" void kernel_launch(void* const* d_in, const int* in_sizes, int n_in,
                              void* d_out, int out_size) {
    const float* inputs = (const float*)d_in[0];   // (B, 8) float32
    const float* qw     = (const float*)d_in[1];   // (3, 3, 2) float32
    float* out          = (float*)d_out;           // (B, 1) float32

    int B = in_sizes[0] / 8;

    build_coeffs<<<1, 32>>>(qw);

    int grid = (B + BLOCK * SPT - 1) / (BLOCK * SPT);   // 512 for B = 2^20

    cudaLaunchConfig_t cfg = {};
    cfg.gridDim = dim3(grid);
    cfg.blockDim = dim3(BLOCK);
    cfg.dynamicSmemBytes = 0;
    cudaLaunchAttribute attr[1];
    attr[0].id = cudaLaunchAttributeProgrammaticStreamSerialization;
    attr[0].val.programmaticStreamSerializationAllowed = 1;
    cfg.attrs = attr;
    cfg.numAttrs = 1;

    cudaLaunchKernelEx(&cfg, vqc_eval, (const float4*)inputs, out, B);
}